// round 16
// baseline (speedup 1.0000x reference)
#include <cuda_runtime.h>
#include <cuda_bf16.h>
#include <cstdint>

#define HH   256
#define WW   256
#define NP   (HH * WW)
#define NG   1024
#define MM   50
#define NCH  150
#define ROWF 160                // padded feature row: 4 quarters x 40 floats
#define TPX  16                 // tile width
#define TPY  4                  // tile height
#define NTX  (WW / TPX)         // 16
#define NTY  (HH / TPY)         // 64
#define NTILES (NTX * NTY)      // 1024
#define CHUNK 16                // gaussians staged per chunk (always full)
#define TRB  150                // transpose blocks (150*256*4 = 153600)

// Scratch (device globals; no allocation allowed)
__device__ __align__(16) float g_params[NG * 8];   // cx, cy, c1, c2, c3, op
__device__ __align__(16) float4 g_bbox[NG];        // x0, x1, y0, y1 (float)
__device__ __align__(16) float g_featT[NG * ROWF]; // [n][160] quarter-padded

// ---------------------------------------------------------------------------
// Kernel A: blocks [0,4) project gaussians -> params + bbox + zero feat pads;
//           blocks [4,154) transpose features (4 elems/thread, MLP=4).
// ---------------------------------------------------------------------------
__global__ void prep(const float* __restrict__ xyz,
                     const float* __restrict__ chol,
                     const float* __restrict__ opac,
                     const float* __restrict__ fdc,
                     const int*   __restrict__ cid_p) {
    const int tid = threadIdx.x;
    if (blockIdx.x < 4) {
        int n = blockIdx.x * 256 + tid;
        float2 xr = ((const float2*)xyz)[n];
        float x  = tanhf(xr.x);
        float y  = tanhf(xr.y);
        float l1 = chol[3 * n + 0] + 0.5f;
        float l2 = chol[3 * n + 1];
        float l3 = chol[3 * n + 2] + 0.5f;
        float a = l1 * l1;
        float b = l1 * l2;
        float c = l2 * l2 + l3 * l3;
        float det = a * c - b * b;
        float c1 = c / det;
        float c2 = -b / det;
        float c3 = a / det;
        float cx = 0.5f * ((x + 1.0f) * (float)WW - 1.0f);
        float cy = 0.5f * ((y + 1.0f) * (float)HH - 1.0f);
        float op = opac[n];
        float4* p = (float4*)&g_params[n * 8];
        p[0] = make_float4(cx, cy, c1, c2);
        p[1] = make_float4(c3, op, 0.0f, 0.0f);
        // alpha >= 1/255 <=> sigma <= T = ln(255*op); ellipse extents + margin
        float T = __logf(255.0f * op);
        if (T > 0.0f) {
            float hx = sqrtf(2.0f * T * a) + 2.0f;
            float hy = sqrtf(2.0f * T * c) + 2.0f;
            g_bbox[n] = make_float4(cx - hx, cx + hx, cy - hy, cy + hy);
        } else {
            g_bbox[n] = make_float4(1e9f, -1e9f, 1e9f, -1e9f);
        }
        float* fr = &g_featT[n * ROWF];              // zero padding slots
        fr[38] = 0.f; fr[39] = 0.f; fr[78] = 0.f; fr[79] = 0.f;
        fr[118] = 0.f; fr[119] = 0.f;
        fr[156] = 0.f; fr[157] = 0.f; fr[158] = 0.f; fr[159] = 0.f;
    } else {
        const int cid = *cid_p;
#pragma unroll
        for (int k = 0; k < 4; k++) {
            int i = (blockIdx.x - 4) * 1024 + k * 256 + tid;  // (t,n), n minor
            int t = i >> 10;                                  // channel 0..149
            int n = i & (NG - 1);
            int m  = t / 3;
            int cc = t - 3 * m;
            float v = fdc[(((size_t)cid * MM + m) * NG + n) * 3 + cc];
            g_featT[n * ROWF + t + 2 * (t / 38)] = v;         // quarter-padded
        }
    }
}

// ---------------------------------------------------------------------------
// Kernel B: render, shuffle-dedup alpha. 256 threads per 16x4 tile.
// Warp = 8 pixels x 4 quarters (lane = q*8+p). Gaussians in groups of 4:
// each lane computes ONE alpha (gaussian base+q, pixel p), distributed by
// __shfl. Channel quarter q is NOT warp-uniform here; feature LDS.128 hits
// 4 distinct addresses x 8-way broadcast (conflict-free).
// ---------------------------------------------------------------------------
__global__ __launch_bounds__(256, 4) void render(float* __restrict__ out) {
    __shared__ unsigned s_mask[32];
    __shared__ int      s_off[32];
    __shared__ int      s_count;
    __shared__ short    s_list[NG];                           // 2 KB
    __shared__ __align__(16) float4 s_feat[CHUNK][ROWF / 4];  // 10 KB
    __shared__ __align__(16) float4 s_cp[CHUNK][2];

    const int tid  = threadIdx.x;
    const int lane = tid & 31;
    const int wid  = tid >> 5;
    const int tile = blockIdx.x;
    const int tx0  = (tile & (NTX - 1)) * TPX;
    const int ty0  = (tile >> 4) * TPY;

    // ---- in-CTA cull: 4 coalesced bbox tests/thread, ordered bitmask ----
    const float fxl = (float)tx0, fxh = (float)(tx0 + TPX - 1);
    const float fyl = (float)ty0, fyh = (float)(ty0 + TPY - 1);
#pragma unroll
    for (int j = 0; j < 4; j++) {
        int g = tid + j * 256;
        float4 bb = g_bbox[g];
        bool hit = (bb.x <= fxh) && (bb.y >= fxl) && (bb.z <= fyh) && (bb.w >= fyl);
        unsigned m = __ballot_sync(0xffffffffu, hit);
        if (lane == 0) s_mask[j * 8 + wid] = m;
    }
    __syncthreads();
    if (tid < 32) {
        int c = __popc(s_mask[tid]);
        int x = c;
#pragma unroll
        for (int d = 1; d < 32; d <<= 1) {
            int y = __shfl_up_sync(0xffffffffu, x, d);
            if (lane >= d) x += y;
        }
        s_off[tid] = x - c;
        if (tid == 31) s_count = x;
    }
    __syncthreads();
    if (tid < 32) {
        unsigned m = s_mask[tid];
        int o = s_off[tid];
        int base = tid * 32;
        while (m) {
            int b = __ffs(m) - 1;
            m &= m - 1;
            s_list[o++] = (short)(base + b);
        }
    }
    __syncthreads();
    const int count = s_count;

    // lane = q*8 + p : p selects pixel within warp's 8, q = channel quarter
    const int p   = lane & 7;
    const int q   = lane >> 3;             // 0..3
    const int pix = wid * 8 + p;           // 0..63
    const float fx = (float)(tx0 + (pix & (TPX - 1)));
    const float fy = (float)(ty0 + (pix >> 4));

    unsigned long long acc[20];
#pragma unroll
    for (int k = 0; k < 20; k++) acc[k] = 0ull;

    for (int c0 = 0; c0 < count; c0 += CHUNK) {
        // ---- stage FULL chunk with clamped indices (uniform control) ----
        for (int i = tid; i < CHUNK * (ROWF / 4); i += 256) {
            int g = i / (ROWF / 4);
            int k = i - g * (ROWF / 4);
            int gi = min(c0 + g, count - 1);
            s_feat[g][k] = ((const float4*)g_featT)[(int)s_list[gi] * (ROWF / 4) + k];
        }
        if (tid < CHUNK * 2) {
            int g = tid >> 1;
            int k = tid & 1;
            int gi = min(c0 + g, count - 1);
            s_cp[g][k] = ((const float4*)g_params)[(int)s_list[gi] * 2 + k];
        }
        __syncthreads();

        // ---- 4 groups of 4 gaussians ----
#pragma unroll
        for (int g4 = 0; g4 < CHUNK / 4; g4++) {
            const int base = g4 * 4;
            // my alpha: gaussian base+q, pixel pix
            float al;
            {
                float4 P0 = s_cp[base + q][0];
                float4 P1 = s_cp[base + q][1];
                float dx = P0.x - fx;
                float dy = P0.y - fy;
                float sig = 0.5f * (P0.z * dx * dx + P1.x * dy * dy) + P0.w * dx * dy;
                al = fminf(0.999f, P1.y * __expf(-sig));
                bool ok = (sig >= 0.0f) && (al >= (1.0f / 255.0f)) &&
                          (c0 + base + q < count);
                al = ok ? al : 0.0f;
            }
#pragma unroll
            for (int j = 0; j < 4; j++) {
                float aj = __shfl_sync(0xffffffffu, al, j * 8 + p);
                unsigned long long ap;
                asm("mov.b64 %0, {%1,%1};" : "=l"(ap) : "r"(__float_as_uint(aj)));
                const ulonglong2* fp =
                    (const ulonglong2*)((const float*)&s_feat[base + j][0] + q * 40);
#pragma unroll
                for (int k = 0; k < 10; k++) {       // 10 x LDS.128
                    ulonglong2 f2 = fp[k];
                    asm("fma.rn.f32x2 %0, %1, %2, %0;" : "+l"(acc[2*k])   : "l"(ap), "l"(f2.x));
                    asm("fma.rn.f32x2 %0, %1, %2, %0;" : "+l"(acc[2*k+1]) : "l"(ap), "l"(f2.y));
                }
            }
        }
        __syncthreads();
    }

    // ---- epilogue: pair k -> channels 38q+2k, 38q+2k+1 (19 real pairs) ----
    const int pofs = (ty0 + (pix >> 4)) * WW + tx0 + (pix & (TPX - 1));
#pragma unroll
    for (int k = 0; k < 19; k++) {
        int ch = q * 38 + 2 * k;
        if (ch + 1 < NCH) {
            unsigned lo, hi;
            asm("mov.b64 {%0,%1}, %2;" : "=r"(lo), "=r"(hi) : "l"(acc[k]));
            out[(size_t)ch       * NP + pofs] = __uint_as_float(lo);
            out[(size_t)(ch + 1) * NP + pofs] = __uint_as_float(hi);
        }
    }
}

// ---------------------------------------------------------------------------
extern "C" void kernel_launch(void* const* d_in, const int* in_sizes, int n_in,
                              void* d_out, int out_size) {
    const float* xyz  = (const float*)d_in[0];  // [N,2]
    const float* chol = (const float*)d_in[1];  // [N,3]
    const float* opac = (const float*)d_in[2];  // [N,1]
    const float* fdc  = (const float*)d_in[3];  // [K,M,N,3]
    const int*   cid  = (const int*)d_in[4];    // scalar

    prep<<<4 + TRB, 256>>>(xyz, chol, opac, fdc, cid);
    render<<<NTILES, 256>>>((float*)d_out);
}

// round 17
// speedup vs baseline: 1.0012x; 1.0012x over previous
#include <cuda_runtime.h>
#include <cuda_bf16.h>
#include <cstdint>

#define HH   256
#define WW   256
#define NP   (HH * WW)
#define NG   1024
#define MM   50
#define NCH  150
#define NCHF 152              // padded channels: 76 f32x2 pairs
#define TPX  16               // tile width
#define TPY  8                // tile height
#define NTX  (WW / TPX)       // 16
#define NTY  (HH / TPY)       // 32
#define HPAIR 38              // f32x2 pairs per half-thread

// Scratch (device globals; no allocation allowed)
__device__ __align__(16) float g_params[NG * 8];   // cx, cy, c1, c2, c3, op
__device__ __align__(16) int4  g_bbox[NG];         // inclusive pixel bbox
__device__ __align__(16) float g_featT[NG * NCHF]; // [n][152] channel-major

// ---------------------------------------------------------------------------
// Prep: blocks 0..3 -> gaussian params+bbox; blocks 4.. -> feature transpose
// (identical to the R4 champion prep)
// ---------------------------------------------------------------------------
__global__ void prep_all(const float* __restrict__ xyz,
                         const float* __restrict__ chol,
                         const float* __restrict__ opac,
                         const float* __restrict__ fdc,
                         const int*   __restrict__ cid_p) {
    const int tid = threadIdx.x;
    if (blockIdx.x < 4) {
        int n = blockIdx.x * 256 + tid;
        float2 xr = ((const float2*)xyz)[n];
        float x  = tanhf(xr.x);
        float y  = tanhf(xr.y);
        float l1 = chol[3 * n + 0] + 0.5f;
        float l2 = chol[3 * n + 1];
        float l3 = chol[3 * n + 2] + 0.5f;
        float a = l1 * l1;
        float b = l1 * l2;
        float c = l2 * l2 + l3 * l3;
        float det = a * c - b * b;
        float c1 = c / det;
        float c2 = -b / det;
        float c3 = a / det;
        float cx = 0.5f * ((x + 1.0f) * (float)WW - 1.0f);
        float cy = 0.5f * ((y + 1.0f) * (float)HH - 1.0f);
        float op = opac[n];
        float4* p = (float4*)&g_params[n * 8];
        p[0] = make_float4(cx, cy, c1, c2);
        p[1] = make_float4(c3, op, 0.0f, 0.0f);

        // alpha >= 1/255 <=> sigma <= T = ln(255*op); ellipse extents
        // hx = sqrt(2*T*Sigma_xx), hy = sqrt(2*T*Sigma_yy); +2 px margin
        int4 bb;
        float T = __logf(255.0f * op);
        if (T > 0.0f) {
            float hx = sqrtf(2.0f * T * a) + 2.0f;
            float hy = sqrtf(2.0f * T * c) + 2.0f;
            bb.x = max(0, (int)floorf(cx - hx));
            bb.y = min(WW - 1, (int)ceilf(cx + hx));
            bb.z = max(0, (int)floorf(cy - hy));
            bb.w = min(HH - 1, (int)ceilf(cy + hy));
        } else {
            bb.x = WW; bb.y = -1; bb.z = HH; bb.w = -1;
        }
        g_bbox[n] = bb;
    } else {
        int i = (blockIdx.x - 4) * 256 + tid;
        if (i < NG * NCHF) {
            int n = i / NCHF;
            int t = i - n * NCHF;
            float v = 0.0f;
            if (t < NCH) {
                int m  = t / 3;
                int cc = t - 3 * m;
                int cid = *cid_p;
                v = fdc[(((size_t)cid * MM + m) * NG + n) * 3 + cc];
            }
            g_featT[i] = v;
        }
    }
}

// ---------------------------------------------------------------------------
// Render: one CTA per 16x8 tile, 2 threads per pixel (half channels each),
// f32x2 packed accumulate, deterministic ordered in-CTA culling.
// R4 champion with: no per-gaussian ballot, float4 param staging.
// ---------------------------------------------------------------------------
__global__ __launch_bounds__(256, 2) void render(float* __restrict__ out) {
    __shared__ unsigned s_mask[32];
    __shared__ int      s_off[32];
    __shared__ int      s_count;
    __shared__ short    s_list[NG];
    __shared__ __align__(16) float4 s_feat[16][NCHF / 4];  // 9.5 KB
    __shared__ __align__(16) float4 s_cp[16][2];

    const int tid  = threadIdx.x;
    const int lane = tid & 31;
    const int wid  = tid >> 5;
    const int tx0  = (blockIdx.x & (NTX - 1)) * TPX;
    const int ty0  = (blockIdx.x >> 4) * TPY;

    // ---- cull: 1024 bbox-vs-tile tests, ordered bitmask ----
#pragma unroll
    for (int j = 0; j < 4; j++) {
        int g = tid + j * 256;
        int4 bb = g_bbox[g];
        bool hit = (bb.x <= tx0 + TPX - 1) && (bb.y >= tx0) &&
                   (bb.z <= ty0 + TPY - 1) && (bb.w >= ty0);
        unsigned m = __ballot_sync(0xffffffffu, hit);
        if (lane == 0) s_mask[j * 8 + wid] = m;
    }
    __syncthreads();
    if (tid < 32) {
        int c = __popc(s_mask[tid]);
        int x = c;
#pragma unroll
        for (int d = 1; d < 32; d <<= 1) {
            int y = __shfl_up_sync(0xffffffffu, x, d);
            if (lane >= d) x += y;
        }
        s_off[tid] = x - c;
        if (tid == 31) s_count = x;
    }
    __syncthreads();
    if (tid < 32) {
        unsigned m = s_mask[tid];
        int o = s_off[tid];
        int base = tid * 32;
        while (m) {
            int b = __ffs(m) - 1;
            m &= m - 1;
            s_list[o++] = (short)(base + b);
        }
    }
    __syncthreads();
    const int count = s_count;

    const int  pix  = tid >> 1;            // 0..127
    const int  half = tid & 1;             // channel half
    const float fx  = (float)(tx0 + (pix & (TPX - 1)));
    const float fy  = (float)(ty0 + (pix >> 4));

    unsigned long long acc[HPAIR];
#pragma unroll
    for (int k = 0; k < HPAIR; k++) acc[k] = 0ull;

    // ---- main loop: chunks of 16 culled gaussians ----
    for (int c0 = 0; c0 < count; c0 += 16) {
        int nc = min(16, count - c0);
        for (int i = tid; i < nc * (NCHF / 4); i += 256) {
            int g = i / (NCHF / 4);
            int k = i - g * (NCHF / 4);
            s_feat[g][k] = ((const float4*)g_featT)[(int)s_list[c0 + g] * (NCHF / 4) + k];
        }
        if (tid < nc * 2) {
            int g = tid >> 1;
            int k = tid & 1;
            s_cp[g][k] = ((const float4*)g_params)[(int)s_list[c0 + g] * 2 + k];
        }
        __syncthreads();

        for (int g = 0; g < nc; g++) {
            float4 P0 = s_cp[g][0];
            float4 P1 = s_cp[g][1];
            float dx = P0.x - fx;
            float dy = P0.y - fy;
            float sig = 0.5f * (P0.z * dx * dx + P1.x * dy * dy) + P0.w * dx * dy;
            float al = fminf(0.999f, P1.y * __expf(-sig));
            al = (sig >= 0.0f && al >= (1.0f / 255.0f)) ? al : 0.0f;
            unsigned long long ap;
            asm("mov.b64 %0, {%1,%1};" : "=l"(ap) : "r"(__float_as_uint(al)));
            // this half's 38 pairs = 76 floats at offset half*76 (16B aligned)
            const ulonglong2* fp =
                (const ulonglong2*)((const float*)&s_feat[g][0] + half * (2 * HPAIR));
#pragma unroll
            for (int k = 0; k < HPAIR / 2; k++) {
                ulonglong2 f2 = fp[k];
                asm("fma.rn.f32x2 %0, %1, %2, %0;" : "+l"(acc[2*k])   : "l"(ap), "l"(f2.x));
                asm("fma.rn.f32x2 %0, %1, %2, %0;" : "+l"(acc[2*k+1]) : "l"(ap), "l"(f2.y));
            }
        }
        __syncthreads();
    }

    // ---- epilogue: unpack, coalesced channel-strided stores ----
    const int pofs = (ty0 + (pix >> 4)) * WW + tx0 + (pix & (TPX - 1));
#pragma unroll
    for (int k = 0; k < HPAIR; k++) {
        int kp = half * HPAIR + k;          // global pair index
        if (kp < NCH / 2) {                 // pair 75 is padding
            unsigned lo, hi;
            asm("mov.b64 {%0,%1}, %2;" : "=r"(lo), "=r"(hi) : "l"(acc[k]));
            out[(size_t)(2 * kp)     * NP + pofs] = __uint_as_float(lo);
            out[(size_t)(2 * kp + 1) * NP + pofs] = __uint_as_float(hi);
        }
    }
}

// ---------------------------------------------------------------------------
extern "C" void kernel_launch(void* const* d_in, const int* in_sizes, int n_in,
                              void* d_out, int out_size) {
    const float* xyz  = (const float*)d_in[0];  // [N,2]
    const float* chol = (const float*)d_in[1];  // [N,3]
    const float* opac = (const float*)d_in[2];  // [N,1]
    const float* fdc  = (const float*)d_in[3];  // [K,M,N,3]
    const int*   cid  = (const int*)d_in[4];    // scalar

    prep_all<<<4 + (NG * NCHF + 255) / 256, 256>>>(xyz, chol, opac, fdc, cid);
    render<<<NTX * NTY, 256>>>((float*)d_out);
}